// round 3
// baseline (speedup 1.0000x reference)
#include <cuda_runtime.h>

#define TILE    32
#define HALO    2
#define REGION  36              // TILE + 2*HALO
#define RPX     (REGION*REGION) // 1296
#define NTHR    256
#define PPT     6               // ceil(1296/256)
#define TSTEPS  96
#define HH      512
#define WW      512
#define PLANE   (HH*WW)

__global__ __launch_bounds__(NTHR)
void clipper_lif_kernel(const float* __restrict__ x,
                        const float* __restrict__ w1,
                        const float* __restrict__ w2,
                        float* __restrict__ out)
{
    const int tid = threadIdx.x;
    const int r0 = blockIdx.y * TILE;
    const int c0 = blockIdx.x * TILE;

    // Per-thread pixel slots over the 36x36 region (tile + conv halo).
    const float* ptr[PPT];
    bool  ok[PPT];
    float v[PPT];
#pragma unroll
    for (int i = 0; i < PPT; i++) {
        int p  = tid + i * NTHR;
        int pr = p / REGION, pc = p % REGION;
        int gr = r0 - HALO + pr;
        int gc = c0 - HALO + pc;
        ok[i]  = (p < RPX) && (gr >= 0) && (gr < HH) && (gc >= 0) && (gc < WW);
        ptr[i] = x + (ok[i] ? (gr * WW + gc) : 0);
        v[i]   = 0.0f;
    }

    // ---------------- FAST PATH ----------------
    // LIF recurrence WITHOUT reset, tracking max(v). Identical to the
    // with-reset trajectory up to (and including) the first threshold
    // crossing, so (m >= 1) <=> "some pixel in this region spikes at
    // some t" with no false positives or negatives.
    float m = 0.0f;
    float xa[PPT], xb[PPT];
#pragma unroll
    for (int i = 0; i < PPT; i++) xa[i] = ok[i] ? ptr[i][0] : 0.0f;

    for (int t = 0; t < TSTEPS; t += 2) {
#pragma unroll
        for (int i = 0; i < PPT; i++)
            xb[i] = ok[i] ? ptr[i][(t + 1) * PLANE] : 0.0f;
#pragma unroll
        for (int i = 0; i < PPT; i++) {
            float d = xa[i] - v[i];
            v[i] = fmaf(d, 0.5f, v[i]);   // bit-exact: v + (x - v)/2
            m = fmaxf(m, v[i]);
        }
        if (t + 2 < TSTEPS) {
#pragma unroll
            for (int i = 0; i < PPT; i++)
                xa[i] = ok[i] ? ptr[i][(t + 2) * PLANE] : 0.0f;
        }
#pragma unroll
        for (int i = 0; i < PPT; i++) {
            float d = xb[i] - v[i];
            v[i] = fmaf(d, 0.5f, v[i]);
            m = fmaxf(m, v[i]);
        }
    }

    int any = __syncthreads_or(m >= 1.0f);
    if (!any) {
        // No spike ever fired in this region => conv(relu(conv(0))) == 0.
#pragma unroll
        for (int k = 0; k < 4; k++) {
            int p = tid + k * NTHR;                 // 1024 outputs / 256 thr
            out[(r0 + (p >> 5)) * WW + (c0 + (p & 31))] = 0.0f;
        }
        return;
    }

    // ---------------- SLOW PATH (cold; correctness insurance) ----------------
    __shared__ float s[REGION][REGION + 1];
    __shared__ float w1s[36], w2s[36];
    if (tid < 36) { w1s[tid] = w1[tid]; w2s[tid] = w2[tid]; }
#pragma unroll
    for (int i = 0; i < PPT; i++) v[i] = 0.0f;
    float ysum[4] = {0.f, 0.f, 0.f, 0.f};
    __syncthreads();

    for (int t = 0; t < TSTEPS; t++) {
#pragma unroll
        for (int i = 0; i < PPT; i++) {
            int p = tid + i * NTHR;
            if (p < RPX) {
                float xv = ok[i] ? ptr[i][t * PLANE] : 0.0f;
                float d  = xv - v[i];
                v[i] = fmaf(d, 0.5f, v[i]);
                float sp = (v[i] >= 1.0f) ? 1.0f : 0.0f;  // v - 1 >= 0
                if (sp != 0.0f) v[i] = 0.0f;               // hard reset
                s[p / REGION][p % REGION] = ok[i] ? sp : 0.0f;
            }
        }
        __syncthreads();

#pragma unroll
        for (int k = 0; k < 4; k++) {
            int p  = tid + k * NTHR;
            int rr = (p >> 5) + HALO;
            int cc = (p & 31) + HALO;
            float y = 0.0f;
#pragma unroll
            for (int d2y = -1; d2y <= 1; d2y++) {
#pragma unroll
                for (int d2x = -1; d2x <= 1; d2x++) {
                    int hr = rr + d2y, hc = cc + d2x;
#pragma unroll
                    for (int c = 0; c < 4; c++) {
                        float h = 0.0f;
#pragma unroll
                        for (int ky = 0; ky < 3; ky++)
#pragma unroll
                            for (int kx = 0; kx < 3; kx++)
                                h += w1s[c * 9 + ky * 3 + kx] *
                                     s[hr + ky - 1][hc + kx - 1];
                        h = fmaxf(h, 0.0f);
                        y += w2s[c * 9 + (d2y + 1) * 3 + (d2x + 1)] * h;
                    }
                }
            }
            ysum[k] += fmaxf(y, 0.0f);
        }
        __syncthreads();
    }

#pragma unroll
    for (int k = 0; k < 4; k++) {
        int p = tid + k * NTHR;
        out[(r0 + (p >> 5)) * WW + (c0 + (p & 31))] =
            ysum[k] * (1.0f / (float)TSTEPS);
    }
}

extern "C" void kernel_launch(void* const* d_in, const int* in_sizes, int n_in,
                              void* d_out, int out_size)
{
    const float* x  = (const float*)d_in[0];   // [96,512,512] f32
    const float* w1 = (const float*)d_in[1];   // [4,1,3,3]  f32
    const float* w2 = (const float*)d_in[2];   // [1,4,3,3]  f32
    float* out = (float*)d_out;                // [512,512]  f32
    (void)in_sizes; (void)n_in; (void)out_size;

    dim3 grid(WW / TILE, HH / TILE);           // 16 x 16
    clipper_lif_kernel<<<grid, NTHR>>>(x, w1, w2, out);
}

// round 12
// speedup vs baseline: 1.6132x; 1.6132x over previous
#include <cuda_runtime.h>

#define TSTEPS  96
#define HH      512
#define WW      512
#define PLANE   (HH*WW)
#define PLANE4  (PLANE/4)        // 65536 float4 groups per timestep
#define NTHR    256

#define TILE    32
#define HALO    2
#define REGION  36
#define RPX     (REGION*REGION)
#define PPT     6

__device__ int g_spike_flag;

// ---------------------------------------------------------------- reset
__global__ void reset_kernel() { g_spike_flag = 0; }

// ---------------------------------------------------------------- scan
// Streaming LIF recurrence WITHOUT reset over every pixel, tracking max(v).
// fmaf(x-v, 0.5f, v) is bit-identical to the reference's v + (x-v)/tau
// (product by 0.5 exact, single rounding), and the no-reset trajectory
// equals the with-reset one up to the first threshold crossing, so
// (max v >= 1) <=> "some pixel spikes at some t", exactly.
__global__ __launch_bounds__(NTHR)
void scan_kernel(const float4* __restrict__ x4)
{
    const int gid = blockIdx.x * NTHR + threadIdx.x;   // [0, 65536)
    const float4* p = x4 + gid;

    float4 v  = make_float4(0.f, 0.f, 0.f, 0.f);
    float4 mx = make_float4(0.f, 0.f, 0.f, 0.f);

    // 8-deep rolling prefetch: 8 outstanding LDG.128 per thread.
    float4 buf[8];
#pragma unroll
    for (int u = 0; u < 8; u++) buf[u] = p[u * PLANE4];

#pragma unroll 1
    for (int c = 0; c < TSTEPS / 8; c++) {
#pragma unroll
        for (int u = 0; u < 8; u++) {
            float4 cur = buf[u];
            int tn = c * 8 + u + 8;
            if (tn < TSTEPS) buf[u] = p[tn * PLANE4];
            v.x = fmaf(cur.x - v.x, 0.5f, v.x);  mx.x = fmaxf(mx.x, v.x);
            v.y = fmaf(cur.y - v.y, 0.5f, v.y);  mx.y = fmaxf(mx.y, v.y);
            v.z = fmaf(cur.z - v.z, 0.5f, v.z);  mx.z = fmaxf(mx.z, v.z);
            v.w = fmaf(cur.w - v.w, 0.5f, v.w);  mx.w = fmaxf(mx.w, v.w);
        }
    }

    float m = fmaxf(fmaxf(mx.x, mx.y), fmaxf(mx.z, mx.w));
    if (__any_sync(0xFFFFFFFFu, m >= 1.0f)) {
        if ((threadIdx.x & 31) == 0) atomicExch(&g_spike_flag, 1);
    }
}

// ---------------------------------------------------------------- output
// flag == 0 (hot): conv(relu(conv(0))) == 0 everywhere -> write zeros.
// flag == 1 (cold insurance): exact per-tile recompute with resets + convs.
__global__ __launch_bounds__(NTHR)
void output_kernel(const float* __restrict__ x,
                   const float* __restrict__ w1,
                   const float* __restrict__ w2,
                   float* __restrict__ out)
{
    const int tid = threadIdx.x;
    const int r0 = blockIdx.y * TILE;
    const int c0 = blockIdx.x * TILE;

    if (g_spike_flag == 0) {
        // 1024 outputs per CTA, float4-vectorized: 256 threads x 1 float4.
        float4* o4 = (float4*)(out + (r0 + (tid >> 3)) * WW + c0) + (tid & 7);
        *o4 = make_float4(0.f, 0.f, 0.f, 0.f);
        return;
    }

    // ---------------- SLOW PATH (cold; correctness insurance) ----------------
    const float* ptr[PPT];
    bool  ok[PPT];
    float v[PPT];
#pragma unroll
    for (int i = 0; i < PPT; i++) {
        int p  = tid + i * NTHR;
        int pr = p / REGION, pc = p % REGION;
        int gr = r0 - HALO + pr;
        int gc = c0 - HALO + pc;
        ok[i]  = (p < RPX) && (gr >= 0) && (gr < HH) && (gc >= 0) && (gc < WW);
        ptr[i] = x + (ok[i] ? (gr * WW + gc) : 0);
        v[i]   = 0.0f;
    }

    __shared__ float s[REGION][REGION + 1];
    __shared__ float w1s[36], w2s[36];
    if (tid < 36) { w1s[tid] = w1[tid]; w2s[tid] = w2[tid]; }
    float ysum[4] = {0.f, 0.f, 0.f, 0.f};
    __syncthreads();

    for (int t = 0; t < TSTEPS; t++) {
#pragma unroll
        for (int i = 0; i < PPT; i++) {
            int p = tid + i * NTHR;
            if (p < RPX) {
                float xv = ok[i] ? ptr[i][t * PLANE] : 0.0f;
                float d  = xv - v[i];
                v[i] = fmaf(d, 0.5f, v[i]);
                float sp = (v[i] >= 1.0f) ? 1.0f : 0.0f;
                if (sp != 0.0f) v[i] = 0.0f;               // hard reset
                s[p / REGION][p % REGION] = ok[i] ? sp : 0.0f;
            }
        }
        __syncthreads();

#pragma unroll
        for (int k = 0; k < 4; k++) {
            int p  = tid + k * NTHR;
            int rr = (p >> 5) + HALO;
            int cc = (p & 31) + HALO;
            float y = 0.0f;
#pragma unroll
            for (int d2y = -1; d2y <= 1; d2y++) {
#pragma unroll
                for (int d2x = -1; d2x <= 1; d2x++) {
                    int hr = rr + d2y, hc = cc + d2x;
#pragma unroll
                    for (int c = 0; c < 4; c++) {
                        float h = 0.0f;
#pragma unroll
                        for (int ky = 0; ky < 3; ky++)
#pragma unroll
                            for (int kx = 0; kx < 3; kx++)
                                h += w1s[c * 9 + ky * 3 + kx] *
                                     s[hr + ky - 1][hc + kx - 1];
                        h = fmaxf(h, 0.0f);
                        y += w2s[c * 9 + (d2y + 1) * 3 + (d2x + 1)] * h;
                    }
                }
            }
            ysum[k] += fmaxf(y, 0.0f);
        }
        __syncthreads();
    }

#pragma unroll
    for (int k = 0; k < 4; k++) {
        int p = tid + k * NTHR;
        out[(r0 + (p >> 5)) * WW + (c0 + (p & 31))] =
            ysum[k] * (1.0f / (float)TSTEPS);
    }
}

extern "C" void kernel_launch(void* const* d_in, const int* in_sizes, int n_in,
                              void* d_out, int out_size)
{
    const float* x  = (const float*)d_in[0];   // [96,512,512] f32
    const float* w1 = (const float*)d_in[1];   // [4,1,3,3]  f32
    const float* w2 = (const float*)d_in[2];   // [1,4,3,3]  f32
    float* out = (float*)d_out;                // [512,512]  f32
    (void)in_sizes; (void)n_in; (void)out_size;

    reset_kernel<<<1, 1>>>();
    scan_kernel<<<PLANE4 / NTHR, NTHR>>>((const float4*)x);   // 256 CTAs
    dim3 grid(WW / TILE, HH / TILE);                          // 16 x 16
    output_kernel<<<grid, NTHR>>>(x, w1, w2, out);
}

// round 16
// speedup vs baseline: 1.6356x; 1.0139x over previous
#include <cuda_runtime.h>

#define TSTEPS  96
#define HH      512
#define WW      512
#define PLANE   (HH*WW)
#define PLANE4  (PLANE/4)        // 65536 float4 groups per timestep
#define NTHR    256
#define NSCAN   (PLANE4/NTHR)    // 256 scan CTAs

#define TILE    32
#define HALO    2
#define REGION  36
#define RPX     (REGION*REGION)
#define PPT     6

// Per-CTA spike flags, written UNCONDITIONALLY by every scan CTA on every
// call -> no reset kernel needed, fully deterministic.
__device__ int g_flags[NSCAN];

// ---------------------------------------------------------------- scan
// Streaming LIF recurrence WITHOUT reset over every pixel, tracking max(v).
// fmaf(x-v, 0.5f, v) is bit-identical to the reference's v + (x-v)/tau
// (product by 0.5 exact, single rounding), and the no-reset trajectory
// equals the with-reset one up to the first threshold crossing, so
// (max v >= 1) <=> "some pixel spikes at some t", exactly.
__global__ __launch_bounds__(NTHR)
void scan_kernel(const float4* __restrict__ x4)
{
    const int gid = blockIdx.x * NTHR + threadIdx.x;   // [0, 65536)
    const float4* p = x4 + gid;

    float4 v  = make_float4(0.f, 0.f, 0.f, 0.f);
    float4 mx = make_float4(0.f, 0.f, 0.f, 0.f);

    // 8-deep rolling prefetch: 8 outstanding LDG.128 per thread.
    float4 buf[8];
#pragma unroll
    for (int u = 0; u < 8; u++) buf[u] = p[u * PLANE4];

#pragma unroll 1
    for (int c = 0; c < TSTEPS / 8; c++) {
#pragma unroll
        for (int u = 0; u < 8; u++) {
            float4 cur = buf[u];
            int tn = c * 8 + u + 8;
            if (tn < TSTEPS) buf[u] = p[tn * PLANE4];
            v.x = fmaf(cur.x - v.x, 0.5f, v.x);  mx.x = fmaxf(mx.x, v.x);
            v.y = fmaf(cur.y - v.y, 0.5f, v.y);  mx.y = fmaxf(mx.y, v.y);
            v.z = fmaf(cur.z - v.z, 0.5f, v.z);  mx.z = fmaxf(mx.z, v.z);
            v.w = fmaf(cur.w - v.w, 0.5f, v.w);  mx.w = fmaxf(mx.w, v.w);
        }
    }

    float m = fmaxf(fmaxf(mx.x, mx.y), fmaxf(mx.z, mx.w));
    int any = __syncthreads_or(m >= 1.0f);
    if (threadIdx.x == 0) g_flags[blockIdx.x] = any;   // unconditional write
}

// ---------------------------------------------------------------- output
// OR of all flags == 0 (hot): conv(relu(conv(0))) == 0 -> write zeros.
// Otherwise (cold insurance): exact per-tile recompute with resets + convs.
__global__ __launch_bounds__(NTHR)
void output_kernel(const float* __restrict__ x,
                   const float* __restrict__ w1,
                   const float* __restrict__ w2,
                   float* __restrict__ out)
{
    const int tid = threadIdx.x;
    const int r0 = blockIdx.y * TILE;
    const int c0 = blockIdx.x * TILE;

    // 256 threads each read one flag (1 KB, L2-resident), block-OR.
    int any = __syncthreads_or(g_flags[tid] != 0);

    if (!any) {
        // 1024 outputs per CTA, float4-vectorized: 256 threads x 1 float4.
        float4* o4 = (float4*)(out + (r0 + (tid >> 3)) * WW + c0) + (tid & 7);
        *o4 = make_float4(0.f, 0.f, 0.f, 0.f);
        return;
    }

    // ---------------- SLOW PATH (cold; correctness insurance) ----------------
    const float* ptr[PPT];
    bool  ok[PPT];
    float v[PPT];
#pragma unroll
    for (int i = 0; i < PPT; i++) {
        int p  = tid + i * NTHR;
        int pr = p / REGION, pc = p % REGION;
        int gr = r0 - HALO + pr;
        int gc = c0 - HALO + pc;
        ok[i]  = (p < RPX) && (gr >= 0) && (gr < HH) && (gc >= 0) && (gc < WW);
        ptr[i] = x + (ok[i] ? (gr * WW + gc) : 0);
        v[i]   = 0.0f;
    }

    __shared__ float s[REGION][REGION + 1];
    __shared__ float w1s[36], w2s[36];
    if (tid < 36) { w1s[tid] = w1[tid]; w2s[tid] = w2[tid]; }
    float ysum[4] = {0.f, 0.f, 0.f, 0.f};
    __syncthreads();

    for (int t = 0; t < TSTEPS; t++) {
#pragma unroll
        for (int i = 0; i < PPT; i++) {
            int p = tid + i * NTHR;
            if (p < RPX) {
                float xv = ok[i] ? ptr[i][t * PLANE] : 0.0f;
                float d  = xv - v[i];
                v[i] = fmaf(d, 0.5f, v[i]);
                float sp = (v[i] >= 1.0f) ? 1.0f : 0.0f;
                if (sp != 0.0f) v[i] = 0.0f;               // hard reset
                s[p / REGION][p % REGION] = ok[i] ? sp : 0.0f;
            }
        }
        __syncthreads();

#pragma unroll
        for (int k = 0; k < 4; k++) {
            int p  = tid + k * NTHR;
            int rr = (p >> 5) + HALO;
            int cc = (p & 31) + HALO;
            float y = 0.0f;
#pragma unroll
            for (int d2y = -1; d2y <= 1; d2y++) {
#pragma unroll
                for (int d2x = -1; d2x <= 1; d2x++) {
                    int hr = rr + d2y, hc = cc + d2x;
#pragma unroll
                    for (int c = 0; c < 4; c++) {
                        float h = 0.0f;
#pragma unroll
                        for (int ky = 0; ky < 3; ky++)
#pragma unroll
                            for (int kx = 0; kx < 3; kx++)
                                h += w1s[c * 9 + ky * 3 + kx] *
                                     s[hr + ky - 1][hc + kx - 1];
                        h = fmaxf(h, 0.0f);
                        y += w2s[c * 9 + (d2y + 1) * 3 + (d2x + 1)] * h;
                    }
                }
            }
            ysum[k] += fmaxf(y, 0.0f);
        }
        __syncthreads();
    }

#pragma unroll
    for (int k = 0; k < 4; k++) {
        int p = tid + k * NTHR;
        out[(r0 + (p >> 5)) * WW + (c0 + (p & 31))] =
            ysum[k] * (1.0f / (float)TSTEPS);
    }
}

extern "C" void kernel_launch(void* const* d_in, const int* in_sizes, int n_in,
                              void* d_out, int out_size)
{
    const float* x  = (const float*)d_in[0];   // [96,512,512] f32
    const float* w1 = (const float*)d_in[1];   // [4,1,3,3]  f32
    const float* w2 = (const float*)d_in[2];   // [1,4,3,3]  f32
    float* out = (float*)d_out;                // [512,512]  f32
    (void)in_sizes; (void)n_in; (void)out_size;

    scan_kernel<<<NSCAN, NTHR>>>((const float4*)x);   // 256 CTAs
    dim3 grid(WW / TILE, HH / TILE);                  // 16 x 16
    output_kernel<<<grid, NTHR>>>(x, w1, w2, out);
}

// round 17
// speedup vs baseline: 1.7927x; 1.0960x over previous
#include <cuda_runtime.h>

#define TSTEPS  96
#define HH      512
#define WW      512
#define PLANE   (HH*WW)
#define PLANE4  (PLANE/4)        // 65536 float4 groups per timestep
#define NTHR    256
#define NSCAN   (PLANE4/NTHR)    // 256 scan CTAs
#define DEPTH   12               // rolling prefetch depth (96 = 8*12)

#define TILE    32
#define HALO    2
#define REGION  36
#define RPX     (REGION*REGION)
#define PPT     6

// Per-CTA spike flags, written UNCONDITIONALLY by every scan CTA on every
// call -> no reset kernel needed, fully deterministic.
__device__ int g_flags[NSCAN];

// ---------------------------------------------------------------- scan
// Streaming LIF recurrence WITHOUT reset over every pixel, tracking max(v).
// fmaf(x-v, 0.5f, v) is bit-identical to the reference's v + (x-v)/tau
// (product by 0.5 exact, single rounding), and the no-reset trajectory
// equals the with-reset one up to the first threshold crossing, so
// (max v >= 1) <=> "some pixel spikes at some t", exactly.
//
// Also speculatively writes the hot-path answer (zeros) for its own two
// output rows: scan CTA b covers linear pixels [b*1024,(b+1)*1024) =
// output rows 2b..2b+1. If any spike exists anywhere, the output kernel's
// cold path overwrites EVERY output pixel, so the speculative zeros are
// only ever final when they are correct.
__global__ __launch_bounds__(NTHR)
void scan_kernel(const float4* __restrict__ x4, float4* __restrict__ out4)
{
    const int tid = threadIdx.x;
    const int gid = blockIdx.x * NTHR + tid;           // [0, 65536)
    const float4* p = x4 + gid;

    // Speculative zero-fill of this CTA's output rows (coalesced STG.128),
    // issued first so it overlaps the read stream.
    out4[gid] = make_float4(0.f, 0.f, 0.f, 0.f);

    float4 v  = make_float4(0.f, 0.f, 0.f, 0.f);
    float4 mx = make_float4(0.f, 0.f, 0.f, 0.f);

    // DEPTH-deep rolling prefetch: DEPTH outstanding LDG.128 per thread.
    float4 buf[DEPTH];
#pragma unroll
    for (int u = 0; u < DEPTH; u++) buf[u] = p[u * PLANE4];

#pragma unroll 1
    for (int c = 0; c < TSTEPS / DEPTH; c++) {
#pragma unroll
        for (int u = 0; u < DEPTH; u++) {
            float4 cur = buf[u];
            int tn = c * DEPTH + u + DEPTH;
            if (tn < TSTEPS) buf[u] = p[tn * PLANE4];
            v.x = fmaf(cur.x - v.x, 0.5f, v.x);  mx.x = fmaxf(mx.x, v.x);
            v.y = fmaf(cur.y - v.y, 0.5f, v.y);  mx.y = fmaxf(mx.y, v.y);
            v.z = fmaf(cur.z - v.z, 0.5f, v.z);  mx.z = fmaxf(mx.z, v.z);
            v.w = fmaf(cur.w - v.w, 0.5f, v.w);  mx.w = fmaxf(mx.w, v.w);
        }
    }

    float m = fmaxf(fmaxf(mx.x, mx.y), fmaxf(mx.z, mx.w));
    int any = __syncthreads_or(m >= 1.0f);
    if (tid == 0) g_flags[blockIdx.x] = any;           // unconditional write
}

// ---------------------------------------------------------------- output
// OR of all flags == 0 (hot): zeros already written by scan -> return.
// Otherwise (cold insurance): exact per-tile recompute with resets + convs,
// overwriting every output pixel.
__global__ __launch_bounds__(NTHR)
void output_kernel(const float* __restrict__ x,
                   const float* __restrict__ w1,
                   const float* __restrict__ w2,
                   float* __restrict__ out)
{
    const int tid = threadIdx.x;
    const int r0 = blockIdx.y * TILE;
    const int c0 = blockIdx.x * TILE;

    // 256 threads each read one flag (1 KB, L2-resident), block-OR.
    int any = __syncthreads_or(g_flags[tid] != 0);
    if (!any) return;                                  // zeros already in out

    // ---------------- SLOW PATH (cold; correctness insurance) ----------------
    const float* ptr[PPT];
    bool  ok[PPT];
    float v[PPT];
#pragma unroll
    for (int i = 0; i < PPT; i++) {
        int p  = tid + i * NTHR;
        int pr = p / REGION, pc = p % REGION;
        int gr = r0 - HALO + pr;
        int gc = c0 - HALO + pc;
        ok[i]  = (p < RPX) && (gr >= 0) && (gr < HH) && (gc >= 0) && (gc < WW);
        ptr[i] = x + (ok[i] ? (gr * WW + gc) : 0);
        v[i]   = 0.0f;
    }

    __shared__ float s[REGION][REGION + 1];
    __shared__ float w1s[36], w2s[36];
    if (tid < 36) { w1s[tid] = w1[tid]; w2s[tid] = w2[tid]; }
    float ysum[4] = {0.f, 0.f, 0.f, 0.f};
    __syncthreads();

    for (int t = 0; t < TSTEPS; t++) {
#pragma unroll
        for (int i = 0; i < PPT; i++) {
            int p = tid + i * NTHR;
            if (p < RPX) {
                float xv = ok[i] ? ptr[i][t * PLANE] : 0.0f;
                float d  = xv - v[i];
                v[i] = fmaf(d, 0.5f, v[i]);
                float sp = (v[i] >= 1.0f) ? 1.0f : 0.0f;
                if (sp != 0.0f) v[i] = 0.0f;               // hard reset
                s[p / REGION][p % REGION] = ok[i] ? sp : 0.0f;
            }
        }
        __syncthreads();

#pragma unroll
        for (int k = 0; k < 4; k++) {
            int p  = tid + k * NTHR;
            int rr = (p >> 5) + HALO;
            int cc = (p & 31) + HALO;
            float y = 0.0f;
#pragma unroll
            for (int d2y = -1; d2y <= 1; d2y++) {
#pragma unroll
                for (int d2x = -1; d2x <= 1; d2x++) {
                    int hr = rr + d2y, hc = cc + d2x;
#pragma unroll
                    for (int c = 0; c < 4; c++) {
                        float h = 0.0f;
#pragma unroll
                        for (int ky = 0; ky < 3; ky++)
#pragma unroll
                            for (int kx = 0; kx < 3; kx++)
                                h += w1s[c * 9 + ky * 3 + kx] *
                                     s[hr + ky - 1][hc + kx - 1];
                        h = fmaxf(h, 0.0f);
                        y += w2s[c * 9 + (d2y + 1) * 3 + (d2x + 1)] * h;
                    }
                }
            }
            ysum[k] += fmaxf(y, 0.0f);
        }
        __syncthreads();
    }

#pragma unroll
    for (int k = 0; k < 4; k++) {
        int p = tid + k * NTHR;
        out[(r0 + (p >> 5)) * WW + (c0 + (p & 31))] =
            ysum[k] * (1.0f / (float)TSTEPS);
    }
}

extern "C" void kernel_launch(void* const* d_in, const int* in_sizes, int n_in,
                              void* d_out, int out_size)
{
    const float* x  = (const float*)d_in[0];   // [96,512,512] f32
    const float* w1 = (const float*)d_in[1];   // [4,1,3,3]  f32
    const float* w2 = (const float*)d_in[2];   // [1,4,3,3]  f32
    float* out = (float*)d_out;                // [512,512]  f32
    (void)in_sizes; (void)n_in; (void)out_size;

    scan_kernel<<<NSCAN, NTHR>>>((const float4*)x, (float4*)out);  // 256 CTAs
    dim3 grid(WW / TILE, HH / TILE);                               // 16 x 16
    output_kernel<<<grid, NTHR>>>(x, w1, w2, out);
}